// round 8
// baseline (speedup 1.0000x reference)
#include <cuda_runtime.h>
#include <cuda_bf16.h>
#include <float.h>
#include <cstdint>

#define N_PTS 131072
#define K_EMB 1024
#define D_DIM 64
#define MT    128          // points per CTA
#define NT    64           // embeddings per chunk
#define NCHUNK (K_EMB / NT)
#define BLOCK 256
#define BUFB  (2 * 8192)   // bytes per B buffer (2 splits x 64x64 bf16)

#define DECAY 0.99f
#define ONE_MINUS_DECAY (1.0f - 0.99f)
#define EPSV 1e-5f

__device__ __forceinline__ uint32_t smem_u32(const void* p) {
    uint32_t a;
    asm("{ .reg .u64 t; cvta.to.shared.u64 t, %1; cvt.u32.u64 %0, t; }"
        : "=r"(a) : "l"(p));
    return a;
}

#define LDMATRIX_X4(r0, r1, r2, r3, addr) \
    asm volatile("ldmatrix.sync.aligned.m8n8.x4.shared.b16 {%0,%1,%2,%3}, [%4];" \
                 : "=r"(r0), "=r"(r1), "=r"(r2), "=r"(r3) : "r"(addr))

#define MMA_BF16(d, a0, a1, a2, a3, b0, b1) \
    asm volatile("mma.sync.aligned.m16n8k16.row.col.f32.bf16.bf16.f32 " \
                 "{%0,%1,%2,%3}, {%4,%5,%6,%7}, {%8,%9}, {%0,%1,%2,%3};" \
                 : "+f"((d)[0]), "+f"((d)[1]), "+f"((d)[2]), "+f"((d)[3]) \
                 : "r"(a0), "r"(a1), "r"(a2), "r"(a3), "r"(b0), "r"(b1))

#define CP_ASYNC16(dst, src) \
    asm volatile("cp.async.cg.shared.global [%0], [%1], 16;" \
                 :: "r"(dst), "l"(src) : "memory")
#define CP_COMMIT() asm volatile("cp.async.commit_group;" ::: "memory")
#define CP_WAIT1()  asm volatile("cp.async.wait_group 1;" ::: "memory")
#define CP_WAIT0()  asm volatile("cp.async.wait_group 0;" ::: "memory")

// -------- scratch (device globals) --------
__device__ float g_counts[K_EMB];
__device__ float g_embed_sum[K_EMB * D_DIM];
__device__ float g_enorm[K_EMB];
__device__ float g_loss_sum;
__device__ int   g_emax2_bits;
__device__ int   g_nflag;
__device__ int   g_flaglist[N_PTS];
__device__ __nv_bfloat16 g_eb[2][K_EMB * D_DIM];   // 2-way bf16 split of embeddings

// -------- zero: tiny init kernel --------
__global__ void zero_kernel() {
    g_loss_sum = 0.f;
    g_nflag = 0;
    g_emax2_bits = 0;
}

// -------- prep: zero scratch, ||e||^2 (+max), bf16 2-split --------
__global__ void prep_kernel(const float* __restrict__ emb) {
    int t = blockIdx.x * blockDim.x + threadIdx.x;   // 65536 threads
    if (t < K_EMB * D_DIM) {
        g_embed_sum[t] = 0.f;
        float v = emb[t];
        __nv_bfloat16 b1 = __float2bfloat16(v);
        float r1 = v - __bfloat162float(b1);
        g_eb[0][t] = b1; g_eb[1][t] = __float2bfloat16(r1);
    }
    if (t < K_EMB) {
        g_counts[t] = 0.f;
        const float4* row = (const float4*)(emb + (size_t)t * D_DIM);
        float s = 0.f;
        #pragma unroll
        for (int q = 0; q < 16; q++) {
            float4 v = row[q];
            s += v.x * v.x + v.y * v.y + v.z * v.z + v.w * v.w;
        }
        g_enorm[t] = s;
        atomicMax(&g_emax2_bits, __float_as_int(s));  // positive floats: int order ok
    }
}

// -------- main: 3-product HMMA scores + certified argmin + epilogue --------
// dynamic smem layout:
//   [0, 2*BUFB)        B double buffer (buf1 aliased as z staging in prologue)
//   [+512)             enorm double buffer (2 x 64 floats)
//   [+512)             s_bidx (128 ints)
//   [+512)             s_gap  (128 floats)
//   [+512)             s_nz2  (128 floats)
//   [+1024)            sred   (256 floats)
#define SMEM_TOTAL (2 * BUFB + 512 + 512 + 512 + 512 + 1024)

__global__ __launch_bounds__(BLOCK, 2) void vq_main(
    const float* __restrict__ z, const float* __restrict__ emb,
    float* __restrict__ out_zq, float* __restrict__ out_idx)
{
    extern __shared__ __align__(16) unsigned char smem[];
    unsigned char* b_s    = smem;
    float*         enorm  = (float*)(smem + 2 * BUFB);
    int*           s_bidx = (int*)  (smem + 2 * BUFB + 512);
    float*         s_gap  = (float*)(smem + 2 * BUFB + 1024);
    float*         s_nz2  = (float*)(smem + 2 * BUFB + 1536);
    float*         sred   = (float*)(smem + 2 * BUFB + 2048);
    unsigned char* zb     = smem + BUFB;          // aliases buffer 1 (prologue only)

    const int t    = threadIdx.x;
    const int warp = t >> 5, lane = t & 31;
    const int g    = lane >> 2, tc = lane & 3;
    const int pt0  = blockIdx.x * MT;
    const uint32_t bs0    = smem_u32(b_s);
    const uint32_t enorm0 = smem_u32(enorm);

    // ---- async stage of chunk c into buffer buf (2 splits) ----
    auto stage = [&](int c, int buf) {
        #pragma unroll
        for (int r = 0; r < 4; r++) {
            int id = t + BLOCK * r;              // 0..1023 16B-units
            int sp = id >> 9, rw = (id >> 3) & 63, u = id & 7;
            const unsigned char* src = (const unsigned char*)g_eb[sp]
                                     + (size_t)c * 8192 + rw * 128 + u * 16;
            uint32_t dst = bs0 + buf * BUFB + sp * 8192 + rw * 128
                         + ((u ^ (rw & 7)) << 4);
            CP_ASYNC16(dst, src);
        }
        if (t < 16) {
            const unsigned char* src = (const unsigned char*)(g_enorm + c * NT) + t * 16;
            CP_ASYNC16(enorm0 + buf * 256 + t * 16, src);
        }
    };

    stage(0, 0);
    CP_COMMIT();

    // ======== A: z 2-split bf16 -> ldmatrix fragments; also ||z||^2 ========
    uint32_t afrag[2][4][4];   // [split][kstep][reg]
    {
        float v[32];
        const int row  = t >> 1;            // 0..127
        const int colh = (t & 1) * 32;      // column half
        {
            const float4* zg = (const float4*)(z + (size_t)(pt0 + row) * D_DIM + colh);
            #pragma unroll
            for (int q = 0; q < 8; q++) {
                float4 w = zg[q];
                v[4 * q] = w.x; v[4 * q + 1] = w.y; v[4 * q + 2] = w.z; v[4 * q + 3] = w.w;
            }
        }
        float nzp = 0.f;
        #pragma unroll
        for (int j = 0; j < 32; j++) nzp += v[j] * v[j];
        nzp += __shfl_xor_sync(0xffffffffu, nzp, 1);
        if ((t & 1) == 0) s_nz2[row] = nzp;

        const uint32_t zb0 = smem_u32(zb);
        #pragma unroll
        for (int s = 0; s < 2; s++) {
            #pragma unroll
            for (int u4 = 0; u4 < 4; u4++) {            // 4 uint4 units of 8 bf16
                uint32_t w[4];
                #pragma unroll
                for (int h = 0; h < 4; h++) {
                    int j = u4 * 8 + 2 * h;
                    __nv_bfloat16 b0 = __float2bfloat16(v[j]);
                    __nv_bfloat16 b1 = __float2bfloat16(v[j + 1]);
                    w[h] = ((uint32_t)__bfloat16_as_ushort(b1) << 16)
                         | (uint32_t)__bfloat16_as_ushort(b0);
                    v[j]     -= __bfloat162float(b0);
                    v[j + 1] -= __bfloat162float(b1);
                }
                int unit = (colh >> 3) + u4;             // 0..7
                *(uint4*)(zb + row * 128 + ((unit ^ (row & 7)) << 4)) =
                    make_uint4(w[0], w[1], w[2], w[3]);
            }
            __syncthreads();
            const int rl = warp * 16 + (lane & 15);
            #pragma unroll
            for (int ks = 0; ks < 4; ks++) {
                int unit = ks * 2 + (lane >> 4);
                uint32_t addr = zb0 + rl * 128 + ((unit ^ (rl & 7)) << 4);
                LDMATRIX_X4(afrag[s][ks][0], afrag[s][ks][1],
                            afrag[s][ks][2], afrag[s][ks][3], addr);
            }
            __syncthreads();
        }
    }

    // per-position best/second-best tracking (positions: row g and row g+8)
    float s1a = FLT_MAX, s2a = FLT_MAX, s1b = FLT_MAX, s2b = FLT_MAX;
    int   i1a = 0, i1b = 0;

    for (int c = 0; c < NCHUNK; c++) {
        const int cur = c & 1;
        if (c + 1 < NCHUNK) {
            stage(c + 1, cur ^ 1);
            CP_COMMIT();
            CP_WAIT1();
        } else {
            CP_WAIT0();
        }
        __syncthreads();

        float acc[8][4];
        #pragma unroll
        for (int nt = 0; nt < 8; nt++)
            #pragma unroll
            for (int i = 0; i < 4; i++) acc[nt][i] = 0.f;

        // products: a1b1, a2b1 (b-split 0), a1b2 (b-split 1)
        #pragma unroll
        for (int s = 0; s < 2; s++) {
            const uint32_t bbase = bs0 + cur * BUFB + s * 8192;
            const int AUSE = (s == 0) ? 2 : 1;
            #pragma unroll
            for (int kh = 0; kh < 2; kh++) {
                uint32_t bb[8][4];
                #pragma unroll
                for (int nt = 0; nt < 8; nt++) {
                    int rw = nt * 8 + (lane & 7);
                    int unit = kh * 4 + (lane >> 3);
                    uint32_t addr = bbase + rw * 128 + ((unit ^ (rw & 7)) << 4);
                    LDMATRIX_X4(bb[nt][0], bb[nt][1], bb[nt][2], bb[nt][3], addr);
                }
                #pragma unroll
                for (int a = 0; a < 2; a++) {
                    if (a < AUSE) {
                        #pragma unroll
                        for (int ks = 0; ks < 2; ks++) {
                            const uint32_t* af = afrag[a][kh * 2 + ks];
                            #pragma unroll
                            for (int nt = 0; nt < 8; nt++)
                                MMA_BF16(acc[nt], af[0], af[1], af[2], af[3],
                                         bb[nt][ks * 2], bb[nt][ks * 2 + 1]);
                        }
                    }
                }
            }
        }

        // ---- scores + running best/second ----
        const float* en = enorm + cur * 64;
        #pragma unroll
        for (int nt = 0; nt < 8; nt++) {
            int nl = nt * 8 + 2 * tc;
            int n0 = c * NT + nl;
            float e0 = en[nl], e1 = en[nl + 1];
            float s00 = fmaf(-2.f, acc[nt][0], e0);
            float s01 = fmaf(-2.f, acc[nt][1], e1);
            float s10 = fmaf(-2.f, acc[nt][2], e0);
            float s11 = fmaf(-2.f, acc[nt][3], e1);
            if (s00 < s1a) { s2a = s1a; s1a = s00; i1a = n0; } else s2a = fminf(s2a, s00);
            if (s01 < s1a) { s2a = s1a; s1a = s01; i1a = n0 + 1; } else s2a = fminf(s2a, s01);
            if (s10 < s1b) { s2b = s1b; s1b = s10; i1b = n0; } else s2b = fminf(s2b, s10);
            if (s11 < s1b) { s2b = s1b; s1b = s11; i1b = n0 + 1; } else s2b = fminf(s2b, s11);
        }
        __syncthreads();
    }

    // ---- quad reduction of (best, idx, second), tie -> flagged via gap 0 ----
    #pragma unroll
    for (int off = 1; off <= 2; off <<= 1) {
        float o1 = __shfl_xor_sync(0xffffffffu, s1a, off);
        int   oi = __shfl_xor_sync(0xffffffffu, i1a, off);
        float o2 = __shfl_xor_sync(0xffffffffu, s2a, off);
        if (o1 < s1a || (o1 == s1a && oi < i1a)) { s2a = fminf(s1a, o2); s1a = o1; i1a = oi; }
        else                                     { s2a = fminf(s2a, o1); }
        o1 = __shfl_xor_sync(0xffffffffu, s1b, off);
        oi = __shfl_xor_sync(0xffffffffu, i1b, off);
        o2 = __shfl_xor_sync(0xffffffffu, s2b, off);
        if (o1 < s1b || (o1 == s1b && oi < i1b)) { s2b = fminf(s1b, o2); s1b = o1; i1b = oi; }
        else                                     { s2b = fminf(s2b, o1); }
    }
    if (tc == 0) {
        s_bidx[warp * 16 + g]     = i1a;  s_gap[warp * 16 + g]     = s2a - s1a;
        s_bidx[warp * 16 + g + 8] = i1b;  s_gap[warp * 16 + g + 8] = s2b - s1b;
    }
    __syncthreads();

    // ---- certification: flag uncertain points for exact fallback ----
    const float emax2 = __int_as_float(g_emax2_bits);
    if (t < MT) {
        float tau = 3.1e-5f * (s_nz2[t] + emax2);
        int b = s_bidx[t];
        if (s_gap[t] <= tau) {
            int slot = atomicAdd(&g_nflag, 1);
            g_flaglist[slot] = pt0 + t;
            s_bidx[t] = -1;
        } else {
            out_idx[pt0 + t] = (float)b;
            atomicAdd(&g_counts[b], 1.f);
        }
    }
    __syncthreads();

    // ---- epilogue for certified points ----
    float lsum = 0.f;
    #pragma unroll
    for (int r = 0; r < 8; r++) {
        int id = t + BLOCK * r;          // 128 pts x 16 float4-units
        int p = id >> 4, q = id & 15;
        int b = s_bidx[p];
        if (b >= 0) {
            int pt = pt0 + p;
            float4 qv = *(const float4*)(emb + (size_t)b * D_DIM + q * 4);
            float4 zv = *(const float4*)(z + (size_t)pt * D_DIM + q * 4);
            *(float4*)(out_zq + (size_t)pt * D_DIM + q * 4) = qv;
            float dx = zv.x - qv.x, dy = zv.y - qv.y;
            float dz2 = zv.z - qv.z, dw = zv.w - qv.w;
            lsum += dx * dx + dy * dy + dz2 * dz2 + dw * dw;
            float* esum = g_embed_sum + (size_t)b * D_DIM + q * 4;
            atomicAdd(esum + 0, zv.x);
            atomicAdd(esum + 1, zv.y);
            atomicAdd(esum + 2, zv.z);
            atomicAdd(esum + 3, zv.w);
        }
    }

    sred[t] = lsum;
    __syncthreads();
    for (int s = BLOCK / 2; s > 0; s >>= 1) {
        if (t < s) sred[t] += sred[t + s];
        __syncthreads();
    }
    if (t == 0) atomicAdd(&g_loss_sum, sred[0]);
}

// -------- fallback: exact fp32 argmin + epilogue for flagged points --------
__global__ __launch_bounds__(256) void fallback_kernel(
    const float* __restrict__ z, const float* __restrict__ emb,
    float* __restrict__ out_zq, float* __restrict__ out_idx)
{
    __shared__ __align__(16) float se[128 * D_DIM];   // 32KB code tile
    __shared__ float sen[128];

    const int nflag = g_nflag;
    if (blockIdx.x * 256 >= nflag) return;
    const int t = threadIdx.x;
    const int my = blockIdx.x * 256 + t;
    const bool act = my < nflag;
    const int pt = act ? g_flaglist[my] : 0;

    float4 zr[16];
    if (act) {
        const float4* zg = (const float4*)(z + (size_t)pt * D_DIM);
        #pragma unroll
        for (int q = 0; q < 16; q++) zr[q] = zg[q];
    }

    float best = FLT_MAX; int bi = 0;
    for (int c = 0; c < 8; c++) {
        __syncthreads();
        const float4* eg = (const float4*)emb + c * 2048;
        #pragma unroll
        for (int r = 0; r < 8; r++) {
            int id = t + 256 * r;
            ((float4*)se)[id] = eg[id];
        }
        if (t < 128) sen[t] = g_enorm[c * 128 + t];
        __syncthreads();

        if (act) {
            for (int e = 0; e < 128; e++) {
                const float4* er = (const float4*)(se + e * D_DIM);
                float a0 = 0.f, a1 = 0.f, a2 = 0.f, a3 = 0.f;
                #pragma unroll
                for (int q = 0; q < 16; q++) {
                    float4 ev = er[q];
                    float4 zv = zr[q];
                    a0 = fmaf(ev.x, zv.x, a0);
                    a1 = fmaf(ev.y, zv.y, a1);
                    a2 = fmaf(ev.z, zv.z, a2);
                    a3 = fmaf(ev.w, zv.w, a3);
                }
                float s = sen[e] - 2.f * ((a0 + a1) + (a2 + a3));
                if (s < best) { best = s; bi = c * 128 + e; }
            }
        }
    }

    if (act) {
        out_idx[pt] = (float)bi;
        atomicAdd(&g_counts[bi], 1.f);
        const float4* qrow = (const float4*)(emb + (size_t)bi * D_DIM);
        float4* orow = (float4*)(out_zq + (size_t)pt * D_DIM);
        float* esum = g_embed_sum + (size_t)bi * D_DIM;
        float lsum = 0.f;
        #pragma unroll
        for (int q = 0; q < 16; q++) {
            float4 qv = qrow[q];
            float4 zv = zr[q];
            orow[q] = qv;
            float dx = zv.x - qv.x, dy = zv.y - qv.y;
            float dz2 = zv.z - qv.z, dw = zv.w - qv.w;
            lsum += dx * dx + dy * dy + dz2 * dz2 + dw * dw;
            atomicAdd(esum + q * 4 + 0, zv.x);
            atomicAdd(esum + q * 4 + 1, zv.y);
            atomicAdd(esum + q * 4 + 2, zv.z);
            atomicAdd(esum + q * 4 + 3, zv.w);
        }
        atomicAdd(&g_loss_sum, lsum);
    }
}

// -------- finalize: EMA updates, normalization, loss mean --------
__global__ __launch_bounds__(1024) void finalize_kernel(
    const float* __restrict__ cluster_size, const float* __restrict__ ema,
    float* __restrict__ out_loss, float* __restrict__ out_nemb,
    float* __restrict__ out_ncs, float* __restrict__ out_nema)
{
    __shared__ float sred[1024];
    const int t = threadIdx.x;   // one CTA, 1024 threads (== K)

    float c = cluster_size[t] * DECAY + ONE_MINUS_DECAY * g_counts[t];
    out_ncs[t] = c;
    sred[t] = c;
    __syncthreads();
    for (int s = 512; s > 0; s >>= 1) {
        if (t < s) sred[t] += sred[t + s];
        __syncthreads();
    }
    float n = sred[0];
    float cs = (c + EPSV) / (n + (float)K_EMB * EPSV) * n;
    float inv = 1.f / cs;

    #pragma unroll 4
    for (int q = 0; q < D_DIM; q++) {
        int idx = t * D_DIM + q;
        float s = ema[idx] * DECAY + ONE_MINUS_DECAY * g_embed_sum[idx];
        out_nema[idx] = s;
        out_nemb[idx] = s * inv;
    }
    if (t == 0) out_loss[0] = g_loss_sum / (float)((size_t)N_PTS * D_DIM);
}

// -------- launch --------
extern "C" void kernel_launch(void* const* d_in, const int* in_sizes, int n_in,
                              void* d_out, int out_size) {
    const float* z   = (const float*)d_in[0];
    const float* emb = (const float*)d_in[1];
    const float* cs  = (const float*)d_in[2];
    const float* ema = (const float*)d_in[3];

    float* out      = (float*)d_out;
    float* out_zq   = out;                               // N*D
    float* out_loss = out + (size_t)N_PTS * D_DIM;       // 1
    float* out_idx  = out_loss + 1;                      // N
    float* out_nemb = out_idx + N_PTS;                   // K*D
    float* out_ncs  = out_nemb + (size_t)K_EMB * D_DIM;  // K
    float* out_nema = out_ncs + K_EMB;                   // K*D

    cudaFuncSetAttribute(vq_main, cudaFuncAttributeMaxDynamicSharedMemorySize,
                         SMEM_TOTAL);

    zero_kernel<<<1, 1>>>();
    prep_kernel<<<256, 256>>>(emb);
    vq_main<<<N_PTS / MT, BLOCK, SMEM_TOTAL>>>(z, emb, out_zq, out_idx);
    fallback_kernel<<<N_PTS / 256, 256>>>(z, emb, out_zq, out_idx);
    finalize_kernel<<<1, 1024>>>(cs, ema, out_loss, out_nemb, out_ncs, out_nema);
}

// round 10
// speedup vs baseline: 1.2874x; 1.2874x over previous
#include <cuda_runtime.h>
#include <cuda_bf16.h>
#include <float.h>
#include <cstdint>

#define N_PTS 131072
#define K_EMB 1024
#define D_DIM 64
#define MT    128          // points per CTA
#define NT    64           // embeddings per chunk
#define NCHUNK (K_EMB / NT)
#define BLOCK 256
#define BUFB  (2 * 8192)   // bytes per B buffer (2 splits x 64x64 bf16)

#define DECAY 0.99f
#define ONE_MINUS_DECAY (1.0f - 0.99f)
#define EPSV 1e-5f

__device__ __forceinline__ uint32_t smem_u32(const void* p) {
    uint32_t a;
    asm("{ .reg .u64 t; cvta.to.shared.u64 t, %1; cvt.u32.u64 %0, t; }"
        : "=r"(a) : "l"(p));
    return a;
}

#define LDMATRIX_X4(r0, r1, r2, r3, addr) \
    asm volatile("ldmatrix.sync.aligned.m8n8.x4.shared.b16 {%0,%1,%2,%3}, [%4];" \
                 : "=r"(r0), "=r"(r1), "=r"(r2), "=r"(r3) : "r"(addr))

#define MMA_BF16(d, a0, a1, a2, a3, b0, b1) \
    asm volatile("mma.sync.aligned.m16n8k16.row.col.f32.bf16.bf16.f32 " \
                 "{%0,%1,%2,%3}, {%4,%5,%6,%7}, {%8,%9}, {%0,%1,%2,%3};" \
                 : "+f"((d)[0]), "+f"((d)[1]), "+f"((d)[2]), "+f"((d)[3]) \
                 : "r"(a0), "r"(a1), "r"(a2), "r"(a3), "r"(b0), "r"(b1))

#define CP_ASYNC16(dst, src) \
    asm volatile("cp.async.cg.shared.global [%0], [%1], 16;" \
                 :: "r"(dst), "l"(src) : "memory")
#define CP_COMMIT() asm volatile("cp.async.commit_group;" ::: "memory")
#define CP_WAIT1()  asm volatile("cp.async.wait_group 1;" ::: "memory")
#define CP_WAIT0()  asm volatile("cp.async.wait_group 0;" ::: "memory")

// -------- scratch (device globals) --------
__device__ float g_counts[K_EMB];
__device__ float g_embed_sum[K_EMB * D_DIM];
__device__ float g_enorm[K_EMB];
__device__ float g_loss_sum;
__device__ int   g_emax2_bits;
__device__ int   g_nflag;
__device__ int   g_flaglist[N_PTS];
__device__ __nv_bfloat16 g_eb[2][K_EMB * D_DIM];   // 2-way bf16 split of embeddings

// -------- zero: tiny init kernel --------
__global__ void zero_kernel() {
    g_loss_sum = 0.f;
    g_nflag = 0;
    g_emax2_bits = 0;
}

// -------- prep: zero scratch, ||e||^2 (+max), bf16 2-split --------
__global__ void prep_kernel(const float* __restrict__ emb) {
    int t = blockIdx.x * blockDim.x + threadIdx.x;   // 65536 threads
    if (t < K_EMB * D_DIM) {
        g_embed_sum[t] = 0.f;
        float v = emb[t];
        __nv_bfloat16 b1 = __float2bfloat16(v);
        float r1 = v - __bfloat162float(b1);
        g_eb[0][t] = b1; g_eb[1][t] = __float2bfloat16(r1);
    }
    if (t < K_EMB) {
        g_counts[t] = 0.f;
        const float4* row = (const float4*)(emb + (size_t)t * D_DIM);
        float s = 0.f;
        #pragma unroll
        for (int q = 0; q < 16; q++) {
            float4 v = row[q];
            s += v.x * v.x + v.y * v.y + v.z * v.z + v.w * v.w;
        }
        g_enorm[t] = s;
        atomicMax(&g_emax2_bits, __float_as_int(s));  // positive floats: int order ok
    }
}

// -------- main: 3-product HMMA scores + certified argmin + epilogue --------
#define SMEM_TOTAL (2 * BUFB + 512 + 512 + 512 + 512 + 1024)

__global__ __launch_bounds__(BLOCK, 2) void vq_main(
    const float* __restrict__ z, const float* __restrict__ emb,
    float* __restrict__ out_zq, float* __restrict__ out_idx)
{
    extern __shared__ __align__(16) unsigned char smem[];
    unsigned char* b_s    = smem;
    float*         enorm  = (float*)(smem + 2 * BUFB);
    int*           s_bidx = (int*)  (smem + 2 * BUFB + 512);
    float*         s_gap  = (float*)(smem + 2 * BUFB + 1024);
    float*         s_nz2  = (float*)(smem + 2 * BUFB + 1536);
    float*         sred   = (float*)(smem + 2 * BUFB + 2048);
    unsigned char* zb     = smem + BUFB;          // aliases buffer 1 (prologue only)

    const int t    = threadIdx.x;
    const int warp = t >> 5, lane = t & 31;
    const int g    = lane >> 2, tc = lane & 3;
    const int pt0  = blockIdx.x * MT;
    const uint32_t bs0    = smem_u32(b_s);
    const uint32_t enorm0 = smem_u32(enorm);

    auto stage = [&](int c, int buf) {
        #pragma unroll
        for (int r = 0; r < 4; r++) {
            int id = t + BLOCK * r;              // 0..1023 16B-units
            int sp = id >> 9, rw = (id >> 3) & 63, u = id & 7;
            const unsigned char* src = (const unsigned char*)g_eb[sp]
                                     + (size_t)c * 8192 + rw * 128 + u * 16;
            uint32_t dst = bs0 + buf * BUFB + sp * 8192 + rw * 128
                         + ((u ^ (rw & 7)) << 4);
            CP_ASYNC16(dst, src);
        }
        if (t < 16) {
            const unsigned char* src = (const unsigned char*)(g_enorm + c * NT) + t * 16;
            CP_ASYNC16(enorm0 + buf * 256 + t * 16, src);
        }
    };

    stage(0, 0);
    CP_COMMIT();

    // ======== A: z 2-split bf16 -> ldmatrix fragments; also ||z||^2 ========
    uint32_t afrag[2][4][4];   // [split][kstep][reg]
    {
        float v[32];
        const int row  = t >> 1;            // 0..127
        const int colh = (t & 1) * 32;      // column half
        {
            const float4* zg = (const float4*)(z + (size_t)(pt0 + row) * D_DIM + colh);
            #pragma unroll
            for (int q = 0; q < 8; q++) {
                float4 w = zg[q];
                v[4 * q] = w.x; v[4 * q + 1] = w.y; v[4 * q + 2] = w.z; v[4 * q + 3] = w.w;
            }
        }
        float nzp = 0.f;
        #pragma unroll
        for (int j = 0; j < 32; j++) nzp += v[j] * v[j];
        nzp += __shfl_xor_sync(0xffffffffu, nzp, 1);
        if ((t & 1) == 0) s_nz2[row] = nzp;

        const uint32_t zb0 = smem_u32(zb);
        #pragma unroll
        for (int s = 0; s < 2; s++) {
            #pragma unroll
            for (int u4 = 0; u4 < 4; u4++) {            // 4 uint4 units of 8 bf16
                uint32_t w[4];
                #pragma unroll
                for (int h = 0; h < 4; h++) {
                    int j = u4 * 8 + 2 * h;
                    __nv_bfloat16 b0 = __float2bfloat16(v[j]);
                    __nv_bfloat16 b1 = __float2bfloat16(v[j + 1]);
                    w[h] = ((uint32_t)__bfloat16_as_ushort(b1) << 16)
                         | (uint32_t)__bfloat16_as_ushort(b0);
                    v[j]     -= __bfloat162float(b0);
                    v[j + 1] -= __bfloat162float(b1);
                }
                int unit = (colh >> 3) + u4;             // 0..7
                *(uint4*)(zb + row * 128 + ((unit ^ (row & 7)) << 4)) =
                    make_uint4(w[0], w[1], w[2], w[3]);
            }
            __syncthreads();
            const int rl = warp * 16 + (lane & 15);
            #pragma unroll
            for (int ks = 0; ks < 4; ks++) {
                int unit = ks * 2 + (lane >> 4);
                uint32_t addr = zb0 + rl * 128 + ((unit ^ (rl & 7)) << 4);
                LDMATRIX_X4(afrag[s][ks][0], afrag[s][ks][1],
                            afrag[s][ks][2], afrag[s][ks][3], addr);
            }
            __syncthreads();
        }
    }

    float s1a = FLT_MAX, s2a = FLT_MAX, s1b = FLT_MAX, s2b = FLT_MAX;
    int   i1a = 0, i1b = 0;

    for (int c = 0; c < NCHUNK; c++) {
        const int cur = c & 1;
        if (c + 1 < NCHUNK) {
            stage(c + 1, cur ^ 1);
            CP_COMMIT();
            CP_WAIT1();
        } else {
            CP_WAIT0();
        }
        __syncthreads();

        float acc[8][4];
        #pragma unroll
        for (int nt = 0; nt < 8; nt++)
            #pragma unroll
            for (int i = 0; i < 4; i++) acc[nt][i] = 0.f;

        // products: a1b1, a2b1 (b-split 0), a1b2 (b-split 1)
        // LOW REGISTER PRESSURE: one LDSM then its MMAs immediately.
        #pragma unroll
        for (int s = 0; s < 2; s++) {
            const uint32_t bbase = bs0 + cur * BUFB + s * 8192;
            #pragma unroll
            for (int kh = 0; kh < 2; kh++) {
                #pragma unroll
                for (int nt = 0; nt < 8; nt++) {
                    uint32_t b0, b1, b2, b3;
                    int rw = nt * 8 + (lane & 7);
                    int unit = kh * 4 + (lane >> 3);
                    uint32_t addr = bbase + rw * 128 + ((unit ^ (rw & 7)) << 4);
                    LDMATRIX_X4(b0, b1, b2, b3, addr);
                    {
                        const uint32_t* af = afrag[0][kh * 2];
                        MMA_BF16(acc[nt], af[0], af[1], af[2], af[3], b0, b1);
                    }
                    {
                        const uint32_t* af = afrag[0][kh * 2 + 1];
                        MMA_BF16(acc[nt], af[0], af[1], af[2], af[3], b2, b3);
                    }
                    if (s == 0) {
                        const uint32_t* af = afrag[1][kh * 2];
                        MMA_BF16(acc[nt], af[0], af[1], af[2], af[3], b0, b1);
                        af = afrag[1][kh * 2 + 1];
                        MMA_BF16(acc[nt], af[0], af[1], af[2], af[3], b2, b3);
                    }
                }
            }
        }

        // ---- scores + running best/second ----
        const float* en = enorm + cur * 64;
        #pragma unroll
        for (int nt = 0; nt < 8; nt++) {
            int nl = nt * 8 + 2 * tc;
            int n0 = c * NT + nl;
            float e0 = en[nl], e1 = en[nl + 1];
            float s00 = fmaf(-2.f, acc[nt][0], e0);
            float s01 = fmaf(-2.f, acc[nt][1], e1);
            float s10 = fmaf(-2.f, acc[nt][2], e0);
            float s11 = fmaf(-2.f, acc[nt][3], e1);
            if (s00 < s1a) { s2a = s1a; s1a = s00; i1a = n0; } else s2a = fminf(s2a, s00);
            if (s01 < s1a) { s2a = s1a; s1a = s01; i1a = n0 + 1; } else s2a = fminf(s2a, s01);
            if (s10 < s1b) { s2b = s1b; s1b = s10; i1b = n0; } else s2b = fminf(s2b, s10);
            if (s11 < s1b) { s2b = s1b; s1b = s11; i1b = n0 + 1; } else s2b = fminf(s2b, s11);
        }
        __syncthreads();
    }

    // ---- quad reduction of (best, idx, second) ----
    #pragma unroll
    for (int off = 1; off <= 2; off <<= 1) {
        float o1 = __shfl_xor_sync(0xffffffffu, s1a, off);
        int   oi = __shfl_xor_sync(0xffffffffu, i1a, off);
        float o2 = __shfl_xor_sync(0xffffffffu, s2a, off);
        if (o1 < s1a || (o1 == s1a && oi < i1a)) { s2a = fminf(s1a, o2); s1a = o1; i1a = oi; }
        else                                     { s2a = fminf(s2a, o1); }
        o1 = __shfl_xor_sync(0xffffffffu, s1b, off);
        oi = __shfl_xor_sync(0xffffffffu, i1b, off);
        o2 = __shfl_xor_sync(0xffffffffu, s2b, off);
        if (o1 < s1b || (o1 == s1b && oi < i1b)) { s2b = fminf(s1b, o2); s1b = o1; i1b = oi; }
        else                                     { s2b = fminf(s2b, o1); }
    }
    if (tc == 0) {
        s_bidx[warp * 16 + g]     = i1a;  s_gap[warp * 16 + g]     = s2a - s1a;
        s_bidx[warp * 16 + g + 8] = i1b;  s_gap[warp * 16 + g + 8] = s2b - s1b;
    }
    __syncthreads();

    // ---- certification: flag uncertain points for exact fallback ----
    const float emax2 = __int_as_float(g_emax2_bits);
    if (t < MT) {
        float tau = 3.1e-5f * (s_nz2[t] + emax2);
        int b = s_bidx[t];
        if (s_gap[t] <= tau) {
            int slot = atomicAdd(&g_nflag, 1);
            g_flaglist[slot] = pt0 + t;
            s_bidx[t] = -1;
        } else {
            out_idx[pt0 + t] = (float)b;
            atomicAdd(&g_counts[b], 1.f);
        }
    }
    __syncthreads();

    // ---- epilogue for certified points ----
    float lsum = 0.f;
    #pragma unroll
    for (int r = 0; r < 8; r++) {
        int id = t + BLOCK * r;          // 128 pts x 16 float4-units
        int p = id >> 4, q = id & 15;
        int b = s_bidx[p];
        if (b >= 0) {
            int pt = pt0 + p;
            float4 qv = *(const float4*)(emb + (size_t)b * D_DIM + q * 4);
            float4 zv = *(const float4*)(z + (size_t)pt * D_DIM + q * 4);
            *(float4*)(out_zq + (size_t)pt * D_DIM + q * 4) = qv;
            float dx = zv.x - qv.x, dy = zv.y - qv.y;
            float dz2 = zv.z - qv.z, dw = zv.w - qv.w;
            lsum += dx * dx + dy * dy + dz2 * dz2 + dw * dw;
            float* esum = g_embed_sum + (size_t)b * D_DIM + q * 4;
            atomicAdd(esum + 0, zv.x);
            atomicAdd(esum + 1, zv.y);
            atomicAdd(esum + 2, zv.z);
            atomicAdd(esum + 3, zv.w);
        }
    }

    sred[t] = lsum;
    __syncthreads();
    for (int s = BLOCK / 2; s > 0; s >>= 1) {
        if (t < s) sred[t] += sred[t + s];
        __syncthreads();
    }
    if (t == 0) atomicAdd(&g_loss_sum, sred[0]);
}

// -------- fallback: warp-per-point exact fp32 argmin + epilogue --------
#define FB_BLOCKS 1024
__global__ __launch_bounds__(256) void fallback_kernel(
    const float* __restrict__ z, const float* __restrict__ emb,
    float* __restrict__ out_zq, float* __restrict__ out_idx)
{
    const int nflag = g_nflag;
    const int lane  = threadIdx.x & 31;
    const int gwarp = (blockIdx.x * 256 + threadIdx.x) >> 5;
    const int nwarp = (FB_BLOCKS * 256) >> 5;   // 8192 warps

    for (int i = gwarp; i < nflag; i += nwarp) {
        const int pt = g_flaglist[i];
        float4 zr[16];
        const float4* zg = (const float4*)(z + (size_t)pt * D_DIM);
        #pragma unroll
        for (int q = 0; q < 16; q++) zr[q] = zg[q];   // broadcast load

        float best = FLT_MAX; int bi = 0;
        for (int c = 0; c < 32; c++) {
            int e = c * 32 + lane;                    // lane-strided codes
            const float4* er = (const float4*)(emb + (size_t)e * D_DIM);
            float a0 = 0.f, a1 = 0.f, a2 = 0.f, a3 = 0.f;
            #pragma unroll
            for (int q = 0; q < 16; q++) {
                float4 ev = er[q];
                a0 = fmaf(ev.x, zr[q].x, a0);
                a1 = fmaf(ev.y, zr[q].y, a1);
                a2 = fmaf(ev.z, zr[q].z, a2);
                a3 = fmaf(ev.w, zr[q].w, a3);
            }
            float s = g_enorm[e] - 2.f * ((a0 + a1) + (a2 + a3));
            if (s < best) { best = s; bi = e; }
        }
        // warp argmin, tie-break toward smaller index
        #pragma unroll
        for (int off = 16; off > 0; off >>= 1) {
            float s2 = __shfl_xor_sync(0xffffffffu, best, off);
            int   b2 = __shfl_xor_sync(0xffffffffu, bi, off);
            if (s2 < best || (s2 == best && b2 < bi)) { best = s2; bi = b2; }
        }

        // cooperative epilogue: lanes 0..15 own one float4 unit each
        float lsum = 0.f;
        if (lane < 16) {
            float4 qv = *(const float4*)(emb + (size_t)bi * D_DIM + lane * 4);
            float4 zv = zr[lane];
            *(float4*)(out_zq + (size_t)pt * D_DIM + lane * 4) = qv;
            float dx = zv.x - qv.x, dy = zv.y - qv.y;
            float dz2 = zv.z - qv.z, dw = zv.w - qv.w;
            lsum = dx * dx + dy * dy + dz2 * dz2 + dw * dw;
            float* esum = g_embed_sum + (size_t)bi * D_DIM + lane * 4;
            atomicAdd(esum + 0, zv.x);
            atomicAdd(esum + 1, zv.y);
            atomicAdd(esum + 2, zv.z);
            atomicAdd(esum + 3, zv.w);
        }
        #pragma unroll
        for (int off = 8; off > 0; off >>= 1)
            lsum += __shfl_xor_sync(0xffffffffu, lsum, off);
        if (lane == 0) {
            out_idx[pt] = (float)bi;
            atomicAdd(&g_counts[bi], 1.f);
            atomicAdd(&g_loss_sum, lsum);
        }
    }
}

// -------- finalize: EMA updates, normalization, loss mean --------
__global__ __launch_bounds__(1024) void finalize_kernel(
    const float* __restrict__ cluster_size, const float* __restrict__ ema,
    float* __restrict__ out_loss, float* __restrict__ out_nemb,
    float* __restrict__ out_ncs, float* __restrict__ out_nema)
{
    __shared__ float sred[1024];
    const int t = threadIdx.x;   // one CTA, 1024 threads (== K)

    float c = cluster_size[t] * DECAY + ONE_MINUS_DECAY * g_counts[t];
    out_ncs[t] = c;
    sred[t] = c;
    __syncthreads();
    for (int s = 512; s > 0; s >>= 1) {
        if (t < s) sred[t] += sred[t + s];
        __syncthreads();
    }
    float n = sred[0];
    float cs = (c + EPSV) / (n + (float)K_EMB * EPSV) * n;
    float inv = 1.f / cs;

    #pragma unroll 4
    for (int q = 0; q < D_DIM; q++) {
        int idx = t * D_DIM + q;
        float s = ema[idx] * DECAY + ONE_MINUS_DECAY * g_embed_sum[idx];
        out_nema[idx] = s;
        out_nemb[idx] = s * inv;
    }
    if (t == 0) out_loss[0] = g_loss_sum / (float)((size_t)N_PTS * D_DIM);
}

// -------- launch --------
extern "C" void kernel_launch(void* const* d_in, const int* in_sizes, int n_in,
                              void* d_out, int out_size) {
    const float* z   = (const float*)d_in[0];
    const float* emb = (const float*)d_in[1];
    const float* cs  = (const float*)d_in[2];
    const float* ema = (const float*)d_in[3];

    float* out      = (float*)d_out;
    float* out_zq   = out;                               // N*D
    float* out_loss = out + (size_t)N_PTS * D_DIM;       // 1
    float* out_idx  = out_loss + 1;                      // N
    float* out_nemb = out_idx + N_PTS;                   // K*D
    float* out_ncs  = out_nemb + (size_t)K_EMB * D_DIM;  // K
    float* out_nema = out_ncs + K_EMB;                   // K*D

    cudaFuncSetAttribute(vq_main, cudaFuncAttributeMaxDynamicSharedMemorySize,
                         SMEM_TOTAL);

    zero_kernel<<<1, 1>>>();
    prep_kernel<<<256, 256>>>(emb);
    vq_main<<<N_PTS / MT, BLOCK, SMEM_TOTAL>>>(z, emb, out_zq, out_idx);
    fallback_kernel<<<FB_BLOCKS, 256>>>(z, emb, out_zq, out_idx);
    finalize_kernel<<<1, 1024>>>(cs, ema, out_loss, out_nemb, out_ncs, out_nema);
}